// round 16
// baseline (speedup 1.0000x reference)
#include <cuda_runtime.h>
#include <cuda_fp16.h>
#include <cstdint>

// Problem constants
#define B_    4
#define M_    4096
#define DM_   1024
#define H_    16
#define HD_   64
#define SEG_  128
#define NSEG_ 32
#define TKV_  64
#define KVROWS (NSEG_ * TKV_)
#define SCALE_ 0.125f
#define KDIM  1024

// ---------------------------------------------------------------------------
// Scratch (device globals: allocation-free per harness rules)
// ---------------------------------------------------------------------------
__device__ __half g_q[(size_t)B_ * H_ * M_ * HD_];
__device__ __half g_kv[(size_t)2 * B_ * H_ * KVROWS * HD_];
__device__ __half g_x_h[(size_t)B_ * M_ * DM_];
__device__ __half g_wqkv_h[3 * DM_ * DM_];
__device__ __half g_wout_h[DM_ * DM_];
__device__ __half g_att_h[(size_t)B_ * M_ * DM_];

// ---------------------------------------------------------------------------
// Helpers (compute_103-safe)
// ---------------------------------------------------------------------------
__device__ __forceinline__ uint32_t smem_to_u32(const void* p) {
    uint32_t a;
    asm("{ .reg .u64 t; cvta.to.shared.u64 t, %1; cvt.u32.u64 %0, t; }" : "=r"(a) : "l"(p));
    return a;
}
#define SWZ128(o) ((o) ^ (((o) >> 3) & 0x70))

__device__ __forceinline__ void cp_async16(uint32_t s, const void* g) {
    asm volatile("cp.async.cg.shared.global [%0], [%1], 16;" :: "r"(s), "l"(g));
}
__device__ __forceinline__ void ldsm_x4(uint32_t* r, uint32_t addr) {
    asm volatile("ldmatrix.sync.aligned.m8n8.x4.shared.b16 {%0,%1,%2,%3}, [%4];"
                 : "=r"(r[0]), "=r"(r[1]), "=r"(r[2]), "=r"(r[3]) : "r"(addr));
}
__device__ __forceinline__ void mma16816(float* d, const uint32_t* a, const uint32_t* b) {
    asm volatile("mma.sync.aligned.m16n8k16.row.col.f32.f16.f16.f32 "
                 "{%0,%1,%2,%3}, {%4,%5,%6,%7}, {%8,%9}, {%0,%1,%2,%3};"
                 : "+f"(d[0]), "+f"(d[1]), "+f"(d[2]), "+f"(d[3])
                 : "r"(a[0]), "r"(a[1]), "r"(a[2]), "r"(a[3]), "r"(b[0]), "r"(b[1]));
}

// ---------------------------------------------------------------------------
// Merged conversion kernel: x (0..16383), Wqkv (16384..19455), Wout (..20479)
// ---------------------------------------------------------------------------
__global__ __launch_bounds__(256) void prep_kernel(const float* __restrict__ x,
                                                   const float* __restrict__ Wqkv,
                                                   const float* __restrict__ Wout) {
    int bid = blockIdx.x;
    int t4 = threadIdx.x * 4;
    const float* src;
    __half* dst;
    int i;
    if (bid < 16384)      { src = x;    dst = g_x_h;    i = bid * 1024 + t4; }
    else if (bid < 19456) { src = Wqkv; dst = g_wqkv_h; i = (bid - 16384) * 1024 + t4; }
    else                  { src = Wout; dst = g_wout_h; i = (bid - 19456) * 1024 + t4; }
    float4 v = *(const float4*)(src + i);
    *(__half2*)(dst + i)     = __halves2half2(__float2half(v.x), __float2half(v.y));
    *(__half2*)(dst + i + 2) = __halves2half2(__float2half(v.z), __float2half(v.w));
}

// ---------------------------------------------------------------------------
// Tensor-core GEMM, single-term fp16, fp32 accum. CTA tile 128x128,
// K-chunk 64, 3-stage cp.async pipeline. 8 warps 2(M)x4(N), warp tile 64x32.
// launch_mode 0: merged Q (blocks 0..1023) + KV (1024..2047).
// launch_mode 1: out projection (fp32 write to Cout).
// smem: 3 stages x 2 tiles (A, B) x 16 KB = 96 KB; 2 CTAs/SM.
// ---------------------------------------------------------------------------
#define TILE_SZ   16384u
#define STAGE_SZ  32768u
#define GEMM_SMEM (3 * 32768)

__global__ __launch_bounds__(256, 2) void gemm_tc_kernel(
    const __half* __restrict__ A,
    const __half* __restrict__ Bq, const __half* __restrict__ Bkv,
    float* __restrict__ Cout, int launch_mode, const int* __restrict__ hmap) {
    extern __shared__ char sm[];
    __shared__ int rowmap[128];
    const uint32_t smb = smem_to_u32(sm);
    const int tid = threadIdx.x;
    const int wid = tid >> 5, lane = tid & 31;
    const int wm = wid & 1, wn = wid >> 1;

    int epi_mode, m0, n0;
    const __half* Bh;
    if (launch_mode == 0) {
        int bid = blockIdx.x;
        if (bid < 1024) { epi_mode = 0; m0 = (bid >> 3) * 128; n0 = (bid & 7) * 128; Bh = Bq; }
        else { bid -= 1024; epi_mode = 1; m0 = (bid >> 4) * 128; n0 = (bid & 15) * 128; Bh = Bkv; }
    } else {
        epi_mode = 2; m0 = (int)(blockIdx.x >> 3) * 128; n0 = (int)(blockIdx.x & 7) * 128;
        Bh = Bq;
    }

    if (tid < 128) {
        int r;
        if (epi_mode == 0) {
            int bb = m0 >> 12, mq = (m0 & 4095) + tid;
            r = bb * M_ + hmap[mq];
        } else if (epi_mode == 1) {
            int bb = m0 >> 11, rr = (m0 & 2047) + tid;
            int s = rr >> 6, t = rr & 63;
            r = bb * M_ + hmap[s * SEG_ + t * 2];
        } else {
            r = m0 + tid;
        }
        rowmap[tid] = r;
    }
    __syncthreads();

    float acc[4][4][4];
#pragma unroll
    for (int mi = 0; mi < 4; mi++)
#pragma unroll
        for (int ni = 0; ni < 4; ni++)
#pragma unroll
            for (int e = 0; e < 4; e++) acc[mi][ni][e] = 0.f;

    const int a_row = wm * 64 + (lane & 15);
    const int a_kb  = (lane >> 4) << 4;
    const int b_row = wn * 32 + ((lane >> 4) << 3) + (lane & 7);
    const int b_kb  = ((lane >> 3) & 1) << 4;

    auto load_chunk = [&](int c, int s) {
        const uint32_t sbase = smb + (uint32_t)s * STAGE_SZ;
#pragma unroll
        for (int tile = 0; tile < 2; tile++) {
            const __half* src = (tile == 0) ? A : Bh;
#pragma unroll
            for (int tt = 0; tt < 4; tt++) {
                int w = tt * 256 + tid;
                int row = w >> 3, g = (w & 7) << 4;
                int grow = (tile == 0) ? rowmap[row] : (n0 + row);
                const char* gp = (const char*)src
                               + ((size_t)grow * KDIM + (size_t)c * 64) * 2 + g;
                uint32_t off = (uint32_t)(row * 128 + g);
                cp_async16(sbase + (uint32_t)tile * TILE_SZ + SWZ128(off), gp);
            }
        }
        asm volatile("cp.async.commit_group;" ::: "memory");
    };

    load_chunk(0, 0);
    load_chunk(1, 1);
    for (int c = 0; c < 16; c++) {
        if (c < 14) {
            load_chunk(c + 2, (c + 2) % 3);
            asm volatile("cp.async.wait_group 2;" ::: "memory");
        } else if (c == 14) {
            asm volatile("cp.async.wait_group 1;" ::: "memory");
        } else {
            asm volatile("cp.async.wait_group 0;" ::: "memory");
        }
        __syncthreads();

        const uint32_t sbase = smb + (uint32_t)(c % 3) * STAGE_SZ;
        const uint32_t tA = sbase, tB = sbase + TILE_SZ;
#pragma unroll
        for (int ks = 0; ks < 4; ks++) {
            uint32_t bhf[2][4];
#pragma unroll
            for (int p = 0; p < 2; p++) {
                uint32_t off = (uint32_t)((b_row + p * 16) * 128 + ks * 32 + b_kb);
                ldsm_x4(bhf[p], tB + SWZ128(off));
            }
#pragma unroll
            for (int mi = 0; mi < 4; mi++) {
                uint32_t af[4];
                uint32_t off = (uint32_t)((a_row + mi * 16) * 128 + ks * 32 + a_kb);
                ldsm_x4(af, tA + SWZ128(off));
#pragma unroll
                for (int ni = 0; ni < 4; ni++)
                    mma16816(acc[mi][ni], af, &bhf[ni >> 1][(ni & 1) * 2]);
            }
        }
        __syncthreads();   // stage free before iter c+1 issues its load
    }

    const int ml = wm * 64 + (lane >> 2);
    const int nl = wn * 32 + ((lane & 3) << 1);
#pragma unroll
    for (int mi = 0; mi < 4; mi++)
#pragma unroll
        for (int ni = 0; ni < 4; ni++)
#pragma unroll
            for (int half = 0; half < 2; half++) {
                int row = m0 + ml + mi * 16 + half * 8;
                int col = n0 + nl + ni * 8;
                float2 v = make_float2(acc[mi][ni][half * 2], acc[mi][ni][half * 2 + 1]);
                if (epi_mode == 0) {
                    int hh = col >> 6, d0 = col & 63;
                    int bb = row >> 12, mq = row & 4095;
                    size_t base = (((size_t)bb * H_ + hh) * (size_t)M_ + mq) * HD_ + d0;
                    *(__half2*)&g_q[base] = __halves2half2(__float2half(v.x * SCALE_),
                                                           __float2half(v.y * SCALE_));
                } else if (epi_mode == 1) {
                    int which = col >> 10, hh = (col & 1023) >> 6, d0 = col & 63;
                    int bb = row >> 11, rr = row & 2047;
                    size_t base = ((((size_t)which * B_ + bb) * H_ + hh) * KVROWS + rr)
                                  * HD_ + d0;
                    *(__half2*)&g_kv[base] = __halves2half2(__float2half(v.x),
                                                            __float2half(v.y));
                } else {
                    *(float2*)&Cout[(size_t)row * 1024 + col] = v;
                }
            }
}

// ---------------------------------------------------------------------------
// Attention on tensor cores (unchanged from R14).
// ---------------------------------------------------------------------------
#define HS_   72
#define HSB_  144
#define OFF_Q 0
#define OFF_K 9216
#define OFF_V 18432
#define OFF_W 27648
#define OFF_S 36864
#define ATT_SMEM (36864 + 64 * 66 * 4)

__global__ __launch_bounds__(256) void hilbert_attn_kernel() {
    extern __shared__ char smc[];
    __half (*VsT)[HS_] = (__half (*)[HS_])(smc + OFF_V);
    __half (*Wh)[HS_]  = (__half (*)[HS_])(smc + OFF_W);
    float  (*Ss)[66]   = (float  (*)[66])(smc + OFF_S);
    __shared__ float part[4][64];
    __shared__ float cmax[64];
    __shared__ float dsum[64];

    const int s = blockIdx.x, h = blockIdx.y, b = blockIdx.z;
    const int tid = threadIdx.x;
    const int wid = tid >> 5, lane = tid & 31;
    const int wm = wid & 1, wn = wid >> 1;
    const int lane64 = tid & 63, quad = tid >> 6;

    const uint32_t smb = smem_to_u32(smc);
    const uint32_t qb = smb + OFF_Q, kb = smb + OFF_K, vb = smb + OFF_V, wb = smb + OFF_W;

    size_t qbase = (((size_t)b * H_ + h) * (size_t)M_ + (size_t)s * SEG_) * HD_;
    size_t kbase = ((((size_t)0 * B_ + b) * H_ + h) * KVROWS + (size_t)s * TKV_) * HD_;
    size_t vbase = ((((size_t)1 * B_ + b) * H_ + h) * KVROWS + (size_t)s * TKV_) * HD_;

    for (int idx = tid; idx < 512; idx += 256) {
        int r = idx >> 3, d8 = (idx & 7) << 3;
        *(uint4*)(smc + OFF_K + r * HSB_ + d8 * 2) =
            *(const uint4*)&g_kv[kbase + (size_t)r * HD_ + d8];
        uint4 vraw = *(const uint4*)&g_kv[vbase + (size_t)r * HD_ + d8];
        const __half* vh = (const __half*)&vraw;
#pragma unroll
        for (int j = 0; j < 8; j++) VsT[d8 + j][r] = vh[j];
    }

    const int a_row = (lane & 15);
    const int a_kb  = (lane >> 4) << 4;
    const int b_row = ((lane >> 4) << 3) + (lane & 7);
    const int b_kb  = ((lane >> 3) & 1) << 4;
    const int ml = wm * 32 + (lane >> 2);
    const int nl = wn * 16 + ((lane & 3) << 1);
    const int q0 = (tid >> 4) << 2;
    const int t0 = (tid & 15) << 2;

    for (int n = 0; n < 2; n++) {
        __syncthreads();
        for (int idx = tid; idx < 512; idx += 256) {
            int r = idx >> 3, d8 = (idx & 7) << 3;
            *(uint4*)(smc + OFF_Q + r * HSB_ + d8 * 2) =
                *(const uint4*)&g_q[qbase + (size_t)(n * 64 + r) * HD_ + d8];
        }
        __syncthreads();

        float acc[2][2][4];
#pragma unroll
        for (int mi = 0; mi < 2; mi++)
#pragma unroll
            for (int ni = 0; ni < 2; ni++)
#pragma unroll
                for (int e = 0; e < 4; e++) acc[mi][ni][e] = 0.f;
#pragma unroll
        for (int ks = 0; ks < 4; ks++) {
            uint32_t bf[4];
            ldsm_x4(bf, kb + (uint32_t)((wn * 16 + b_row) * HSB_ + ks * 32 + b_kb));
#pragma unroll
            for (int mi = 0; mi < 2; mi++) {
                uint32_t af[4];
                ldsm_x4(af, qb + (uint32_t)((wm * 32 + mi * 16 + a_row) * HSB_ + ks * 32 + a_kb));
                mma16816(acc[mi][0], af, &bf[0]);
                mma16816(acc[mi][1], af, &bf[2]);
            }
        }
#pragma unroll
        for (int mi = 0; mi < 2; mi++)
#pragma unroll
            for (int ni = 0; ni < 2; ni++)
#pragma unroll
                for (int half = 0; half < 2; half++)
                    *(float2*)&Ss[ml + mi * 16 + half * 8][nl + ni * 8] =
                        make_float2(acc[mi][ni][half * 2], acc[mi][ni][half * 2 + 1]);
        __syncthreads();

        {
            float mx = -1e30f;
#pragma unroll
            for (int q = quad * 16; q < quad * 16 + 16; q++)
                mx = fmaxf(mx, Ss[q][lane64]);
            part[quad][lane64] = mx;
        }
        __syncthreads();
        if (tid < 64)
            cmax[tid] = fmaxf(fmaxf(part[0][tid], part[1][tid]),
                              fmaxf(part[2][tid], part[3][tid]));
        __syncthreads();

#pragma unroll
        for (int i = 0; i < 4; i++) {
            float e0 = __expf(Ss[q0 + i][t0 + 0] - cmax[t0 + 0]);
            float e1 = __expf(Ss[q0 + i][t0 + 1] - cmax[t0 + 1]);
            float e2 = __expf(Ss[q0 + i][t0 + 2] - cmax[t0 + 2]);
            float e3 = __expf(Ss[q0 + i][t0 + 3] - cmax[t0 + 3]);
            Ss[q0 + i][t0 + 0] = e0; Ss[q0 + i][t0 + 1] = e1;
            Ss[q0 + i][t0 + 2] = e2; Ss[q0 + i][t0 + 3] = e3;
            *(__half2*)&Wh[q0 + i][t0]     = __halves2half2(__float2half(e0), __float2half(e1));
            *(__half2*)&Wh[q0 + i][t0 + 2] = __halves2half2(__float2half(e2), __float2half(e3));
        }
        __syncthreads();

        {
            float sum = 0.f;
#pragma unroll
            for (int t = quad * 16; t < quad * 16 + 16; t++)
                sum += Ss[lane64][t];
            part[quad][lane64] = sum;
        }
        __syncthreads();
        if (tid < 64)
            dsum[tid] = 1e-10f + ((part[0][tid] + part[1][tid])
                                + (part[2][tid] + part[3][tid]));
        __syncthreads();

        float oac[2][2][4];
#pragma unroll
        for (int mi = 0; mi < 2; mi++)
#pragma unroll
            for (int ni = 0; ni < 2; ni++)
#pragma unroll
                for (int e = 0; e < 4; e++) oac[mi][ni][e] = 0.f;
#pragma unroll
        for (int ks = 0; ks < 4; ks++) {
            uint32_t bf[4];
            ldsm_x4(bf, vb + (uint32_t)((wn * 16 + b_row) * HSB_ + ks * 32 + b_kb));
#pragma unroll
            for (int mi = 0; mi < 2; mi++) {
                uint32_t af[4];
                ldsm_x4(af, wb + (uint32_t)((wm * 32 + mi * 16 + a_row) * HSB_ + ks * 32 + a_kb));
                mma16816(oac[mi][0], af, &bf[0]);
                mma16816(oac[mi][1], af, &bf[2]);
            }
        }
#pragma unroll
        for (int mi = 0; mi < 2; mi++)
#pragma unroll
            for (int half = 0; half < 2; half++) {
                int q = ml + mi * 16 + half * 8;
                float inv = 1.0f / dsum[q];
                int m = s * SEG_ + n * 64 + q;
                size_t o = ((size_t)(b * M_ + m)) * DM_ + h * HD_;
#pragma unroll
                for (int ni = 0; ni < 2; ni++) {
                    int d = nl + ni * 8;
                    *(__half2*)&g_att_h[o + d] =
                        __halves2half2(__float2half(oac[mi][ni][half * 2] * inv),
                                       __float2half(oac[mi][ni][half * 2 + 1] * inv));
                }
            }
    }
}

// ---------------------------------------------------------------------------

extern "C" void kernel_launch(void* const* d_in, const int* in_sizes, int n_in,
                              void* d_out, int out_size) {
    const float* x    = (const float*)d_in[0];
    const float* Wqkv = (const float*)d_in[1];
    const float* Wout = (const float*)d_in[2];
    const int*   hmap = (const int*)d_in[3];
    float* out = (float*)d_out;
    (void)in_sizes; (void)n_in; (void)out_size;

    __half *xh, *qh, *oh, *ah;
    cudaGetSymbolAddress((void**)&xh, g_x_h);
    cudaGetSymbolAddress((void**)&qh, g_wqkv_h);
    cudaGetSymbolAddress((void**)&oh, g_wout_h);
    cudaGetSymbolAddress((void**)&ah, g_att_h);

    // 0) merged fp16 conversions
    prep_kernel<<<20480, 256>>>(x, Wqkv, Wout);

    cudaFuncSetAttribute((const void*)gemm_tc_kernel,
                         cudaFuncAttributeMaxDynamicSharedMemorySize, GEMM_SMEM);

    // 1) Merged Q + KV projection (2048 CTAs, 1-term, 3-stage)
    gemm_tc_kernel<<<2048, 256, GEMM_SMEM>>>(xh, qh, qh + 1024 * 1024,
                                             nullptr, 0, hmap);

    // 2) Hilbert segmented attention (tensor-core matmuls)
    cudaFuncSetAttribute((const void*)hilbert_attn_kernel,
                         cudaFuncAttributeMaxDynamicSharedMemorySize, ATT_SMEM);
    hilbert_attn_kernel<<<dim3(NSEG_, H_, B_), 256, ATT_SMEM>>>();

    // 3) Output projection (1024 CTAs, 1-term, 3-stage)
    gemm_tc_kernel<<<1024, 256, GEMM_SMEM>>>(ah, oh, nullptr, out, 1, hmap);
}

// round 17
// speedup vs baseline: 1.5825x; 1.5825x over previous
#include <cuda_runtime.h>
#include <cuda_fp16.h>
#include <cstdint>

// Problem constants
#define B_    4
#define M_    4096
#define DM_   1024
#define H_    16
#define HD_   64
#define SEG_  128
#define NSEG_ 32
#define TKV_  64
#define KVROWS (NSEG_ * TKV_)
#define SCALE_ 0.125f
#define KDIM  1024

// ---------------------------------------------------------------------------
// Scratch (device globals: allocation-free per harness rules)
// ---------------------------------------------------------------------------
__device__ __half g_q[(size_t)B_ * H_ * M_ * HD_];
__device__ __half g_kv[(size_t)2 * B_ * H_ * KVROWS * HD_];
__device__ __half g_x_h[(size_t)B_ * M_ * DM_];
__device__ __half g_wqkv_h[3 * DM_ * DM_];
__device__ __half g_wout_h[DM_ * DM_];
__device__ __half g_att_h[(size_t)B_ * M_ * DM_];

// ---------------------------------------------------------------------------
// Helpers (compute_103-safe)
// ---------------------------------------------------------------------------
__device__ __forceinline__ uint32_t smem_to_u32(const void* p) {
    uint32_t a;
    asm("{ .reg .u64 t; cvta.to.shared.u64 t, %1; cvt.u32.u64 %0, t; }" : "=r"(a) : "l"(p));
    return a;
}
#define SWZ128(o) ((o) ^ (((o) >> 3) & 0x70))

__device__ __forceinline__ void cp_async16(uint32_t s, const void* g) {
    asm volatile("cp.async.cg.shared.global [%0], [%1], 16;" :: "r"(s), "l"(g));
}
__device__ __forceinline__ void ldsm_x4(uint32_t* r, uint32_t addr) {
    asm volatile("ldmatrix.sync.aligned.m8n8.x4.shared.b16 {%0,%1,%2,%3}, [%4];"
                 : "=r"(r[0]), "=r"(r[1]), "=r"(r[2]), "=r"(r[3]) : "r"(addr));
}
__device__ __forceinline__ void mma16816(float* d, const uint32_t* a, const uint32_t* b) {
    asm volatile("mma.sync.aligned.m16n8k16.row.col.f32.f16.f16.f32 "
                 "{%0,%1,%2,%3}, {%4,%5,%6,%7}, {%8,%9}, {%0,%1,%2,%3};"
                 : "+f"(d[0]), "+f"(d[1]), "+f"(d[2]), "+f"(d[3])
                 : "r"(a[0]), "r"(a[1]), "r"(a[2]), "r"(a[3]), "r"(b[0]), "r"(b[1]));
}

// ---------------------------------------------------------------------------
// Merged conversion kernel: x (0..16383), Wqkv (16384..19455), Wout (..20479)
// ---------------------------------------------------------------------------
__global__ __launch_bounds__(256) void prep_kernel(const float* __restrict__ x,
                                                   const float* __restrict__ Wqkv,
                                                   const float* __restrict__ Wout) {
    int bid = blockIdx.x;
    int t4 = threadIdx.x * 4;
    const float* src;
    __half* dst;
    int i;
    if (bid < 16384)      { src = x;    dst = g_x_h;    i = bid * 1024 + t4; }
    else if (bid < 19456) { src = Wqkv; dst = g_wqkv_h; i = (bid - 16384) * 1024 + t4; }
    else                  { src = Wout; dst = g_wout_h; i = (bid - 19456) * 1024 + t4; }
    float4 v = *(const float4*)(src + i);
    *(__half2*)(dst + i)     = __halves2half2(__float2half(v.x), __float2half(v.y));
    *(__half2*)(dst + i + 2) = __halves2half2(__float2half(v.z), __float2half(v.w));
}

// ---------------------------------------------------------------------------
// Tensor-core GEMM, single-term fp16, fp32 accum. CTA tile 128x128,
// K-chunk 64, 2-stage cp.async (the measured-best pipeline depth).
// 8 warps 2(M)x4(N), warp tile 64x32.
// launch_mode 0: merged Q (blocks 0..1023) + KV (1024..2047).
// launch_mode 1: out projection (fp32 write to Cout).
// smem: 2 stages x 2 tiles x 16 KB = 64 KB; 2 CTAs/SM.
// ---------------------------------------------------------------------------
#define TILE_SZ   16384u
#define STAGE_SZ  32768u
#define GEMM_SMEM (2 * 32768)

__global__ __launch_bounds__(256, 2) void gemm_tc_kernel(
    const __half* __restrict__ A,
    const __half* __restrict__ Bq, const __half* __restrict__ Bkv,
    float* __restrict__ Cout, int launch_mode, const int* __restrict__ hmap) {
    extern __shared__ char sm[];
    __shared__ int rowmap[128];
    const uint32_t smb = smem_to_u32(sm);
    const int tid = threadIdx.x;
    const int wid = tid >> 5, lane = tid & 31;
    const int wm = wid & 1, wn = wid >> 1;

    int epi_mode, m0, n0;
    const __half* Bh;
    if (launch_mode == 0) {
        int bid = blockIdx.x;
        if (bid < 1024) { epi_mode = 0; m0 = (bid >> 3) * 128; n0 = (bid & 7) * 128; Bh = Bq; }
        else { bid -= 1024; epi_mode = 1; m0 = (bid >> 4) * 128; n0 = (bid & 15) * 128; Bh = Bkv; }
    } else {
        epi_mode = 2; m0 = (int)(blockIdx.x >> 3) * 128; n0 = (int)(blockIdx.x & 7) * 128;
        Bh = Bq;
    }

    if (tid < 128) {
        int r;
        if (epi_mode == 0) {
            int bb = m0 >> 12, mq = (m0 & 4095) + tid;
            r = bb * M_ + hmap[mq];
        } else if (epi_mode == 1) {
            int bb = m0 >> 11, rr = (m0 & 2047) + tid;
            int s = rr >> 6, t = rr & 63;
            r = bb * M_ + hmap[s * SEG_ + t * 2];
        } else {
            r = m0 + tid;
        }
        rowmap[tid] = r;
    }
    __syncthreads();

    float acc[4][4][4];
#pragma unroll
    for (int mi = 0; mi < 4; mi++)
#pragma unroll
        for (int ni = 0; ni < 4; ni++)
#pragma unroll
            for (int e = 0; e < 4; e++) acc[mi][ni][e] = 0.f;

    const int a_row = wm * 64 + (lane & 15);
    const int a_kb  = (lane >> 4) << 4;
    const int b_row = wn * 32 + ((lane >> 4) << 3) + (lane & 7);
    const int b_kb  = ((lane >> 3) & 1) << 4;

    auto load_chunk = [&](int c, int s) {
        const uint32_t sbase = smb + (uint32_t)s * STAGE_SZ;
#pragma unroll
        for (int tile = 0; tile < 2; tile++) {
            const __half* src = (tile == 0) ? A : Bh;
#pragma unroll
            for (int tt = 0; tt < 4; tt++) {
                int w = tt * 256 + tid;
                int row = w >> 3, g = (w & 7) << 4;
                int grow = (tile == 0) ? rowmap[row] : (n0 + row);
                const char* gp = (const char*)src
                               + ((size_t)grow * KDIM + (size_t)c * 64) * 2 + g;
                uint32_t off = (uint32_t)(row * 128 + g);
                cp_async16(sbase + (uint32_t)tile * TILE_SZ + SWZ128(off), gp);
            }
        }
        asm volatile("cp.async.commit_group;" ::: "memory");
    };

    load_chunk(0, 0);
    for (int c = 0; c < 16; c++) {
        if (c < 15) {
            load_chunk(c + 1, (c + 1) & 1);
            asm volatile("cp.async.wait_group 1;" ::: "memory");
        } else {
            asm volatile("cp.async.wait_group 0;" ::: "memory");
        }
        __syncthreads();

        const uint32_t sbase = smb + (uint32_t)(c & 1) * STAGE_SZ;
        const uint32_t tA = sbase, tB = sbase + TILE_SZ;
#pragma unroll
        for (int ks = 0; ks < 4; ks++) {
            uint32_t bhf[2][4];
#pragma unroll
            for (int p = 0; p < 2; p++) {
                uint32_t off = (uint32_t)((b_row + p * 16) * 128 + ks * 32 + b_kb);
                ldsm_x4(bhf[p], tB + SWZ128(off));
            }
#pragma unroll
            for (int mi = 0; mi < 4; mi++) {
                uint32_t af[4];
                uint32_t off = (uint32_t)((a_row + mi * 16) * 128 + ks * 32 + a_kb);
                ldsm_x4(af, tA + SWZ128(off));
#pragma unroll
                for (int ni = 0; ni < 4; ni++)
                    mma16816(acc[mi][ni], af, &bhf[ni >> 1][(ni & 1) * 2]);
            }
        }
        __syncthreads();
    }

    const int ml = wm * 64 + (lane >> 2);
    const int nl = wn * 32 + ((lane & 3) << 1);
#pragma unroll
    for (int mi = 0; mi < 4; mi++)
#pragma unroll
        for (int ni = 0; ni < 4; ni++)
#pragma unroll
            for (int half = 0; half < 2; half++) {
                int row = m0 + ml + mi * 16 + half * 8;
                int col = n0 + nl + ni * 8;
                float2 v = make_float2(acc[mi][ni][half * 2], acc[mi][ni][half * 2 + 1]);
                if (epi_mode == 0) {
                    int hh = col >> 6, d0 = col & 63;
                    int bb = row >> 12, mq = row & 4095;
                    size_t base = (((size_t)bb * H_ + hh) * (size_t)M_ + mq) * HD_ + d0;
                    *(__half2*)&g_q[base] = __halves2half2(__float2half(v.x * SCALE_),
                                                           __float2half(v.y * SCALE_));
                } else if (epi_mode == 1) {
                    int which = col >> 10, hh = (col & 1023) >> 6, d0 = col & 63;
                    int bb = row >> 11, rr = row & 2047;
                    size_t base = ((((size_t)which * B_ + bb) * H_ + hh) * KVROWS + rr)
                                  * HD_ + d0;
                    *(__half2*)&g_kv[base] = __halves2half2(__float2half(v.x),
                                                            __float2half(v.y));
                } else {
                    *(float2*)&Cout[(size_t)row * 1024 + col] = v;
                }
            }
}

// ---------------------------------------------------------------------------
// Attention on tensor cores (unchanged from R14).
// ---------------------------------------------------------------------------
#define HS_   72
#define HSB_  144
#define OFF_Q 0
#define OFF_K 9216
#define OFF_V 18432
#define OFF_W 27648
#define OFF_S 36864
#define ATT_SMEM (36864 + 64 * 66 * 4)

__global__ __launch_bounds__(256) void hilbert_attn_kernel() {
    extern __shared__ char smc[];
    __half (*VsT)[HS_] = (__half (*)[HS_])(smc + OFF_V);
    __half (*Wh)[HS_]  = (__half (*)[HS_])(smc + OFF_W);
    float  (*Ss)[66]   = (float  (*)[66])(smc + OFF_S);
    __shared__ float part[4][64];
    __shared__ float cmax[64];
    __shared__ float dsum[64];

    const int s = blockIdx.x, h = blockIdx.y, b = blockIdx.z;
    const int tid = threadIdx.x;
    const int wid = tid >> 5, lane = tid & 31;
    const int wm = wid & 1, wn = wid >> 1;
    const int lane64 = tid & 63, quad = tid >> 6;

    const uint32_t smb = smem_to_u32(smc);
    const uint32_t qb = smb + OFF_Q, kb = smb + OFF_K, vb = smb + OFF_V, wb = smb + OFF_W;

    size_t qbase = (((size_t)b * H_ + h) * (size_t)M_ + (size_t)s * SEG_) * HD_;
    size_t kbase = ((((size_t)0 * B_ + b) * H_ + h) * KVROWS + (size_t)s * TKV_) * HD_;
    size_t vbase = ((((size_t)1 * B_ + b) * H_ + h) * KVROWS + (size_t)s * TKV_) * HD_;

    for (int idx = tid; idx < 512; idx += 256) {
        int r = idx >> 3, d8 = (idx & 7) << 3;
        *(uint4*)(smc + OFF_K + r * HSB_ + d8 * 2) =
            *(const uint4*)&g_kv[kbase + (size_t)r * HD_ + d8];
        uint4 vraw = *(const uint4*)&g_kv[vbase + (size_t)r * HD_ + d8];
        const __half* vh = (const __half*)&vraw;
#pragma unroll
        for (int j = 0; j < 8; j++) VsT[d8 + j][r] = vh[j];
    }

    const int a_row = (lane & 15);
    const int a_kb  = (lane >> 4) << 4;
    const int b_row = ((lane >> 4) << 3) + (lane & 7);
    const int b_kb  = ((lane >> 3) & 1) << 4;
    const int ml = wm * 32 + (lane >> 2);
    const int nl = wn * 16 + ((lane & 3) << 1);
    const int q0 = (tid >> 4) << 2;
    const int t0 = (tid & 15) << 2;

    for (int n = 0; n < 2; n++) {
        __syncthreads();
        for (int idx = tid; idx < 512; idx += 256) {
            int r = idx >> 3, d8 = (idx & 7) << 3;
            *(uint4*)(smc + OFF_Q + r * HSB_ + d8 * 2) =
                *(const uint4*)&g_q[qbase + (size_t)(n * 64 + r) * HD_ + d8];
        }
        __syncthreads();

        float acc[2][2][4];
#pragma unroll
        for (int mi = 0; mi < 2; mi++)
#pragma unroll
            for (int ni = 0; ni < 2; ni++)
#pragma unroll
                for (int e = 0; e < 4; e++) acc[mi][ni][e] = 0.f;
#pragma unroll
        for (int ks = 0; ks < 4; ks++) {
            uint32_t bf[4];
            ldsm_x4(bf, kb + (uint32_t)((wn * 16 + b_row) * HSB_ + ks * 32 + b_kb));
#pragma unroll
            for (int mi = 0; mi < 2; mi++) {
                uint32_t af[4];
                ldsm_x4(af, qb + (uint32_t)((wm * 32 + mi * 16 + a_row) * HSB_ + ks * 32 + a_kb));
                mma16816(acc[mi][0], af, &bf[0]);
                mma16816(acc[mi][1], af, &bf[2]);
            }
        }
#pragma unroll
        for (int mi = 0; mi < 2; mi++)
#pragma unroll
            for (int ni = 0; ni < 2; ni++)
#pragma unroll
                for (int half = 0; half < 2; half++)
                    *(float2*)&Ss[ml + mi * 16 + half * 8][nl + ni * 8] =
                        make_float2(acc[mi][ni][half * 2], acc[mi][ni][half * 2 + 1]);
        __syncthreads();

        {
            float mx = -1e30f;
#pragma unroll
            for (int q = quad * 16; q < quad * 16 + 16; q++)
                mx = fmaxf(mx, Ss[q][lane64]);
            part[quad][lane64] = mx;
        }
        __syncthreads();
        if (tid < 64)
            cmax[tid] = fmaxf(fmaxf(part[0][tid], part[1][tid]),
                              fmaxf(part[2][tid], part[3][tid]));
        __syncthreads();

#pragma unroll
        for (int i = 0; i < 4; i++) {
            float e0 = __expf(Ss[q0 + i][t0 + 0] - cmax[t0 + 0]);
            float e1 = __expf(Ss[q0 + i][t0 + 1] - cmax[t0 + 1]);
            float e2 = __expf(Ss[q0 + i][t0 + 2] - cmax[t0 + 2]);
            float e3 = __expf(Ss[q0 + i][t0 + 3] - cmax[t0 + 3]);
            Ss[q0 + i][t0 + 0] = e0; Ss[q0 + i][t0 + 1] = e1;
            Ss[q0 + i][t0 + 2] = e2; Ss[q0 + i][t0 + 3] = e3;
            *(__half2*)&Wh[q0 + i][t0]     = __halves2half2(__float2half(e0), __float2half(e1));
            *(__half2*)&Wh[q0 + i][t0 + 2] = __halves2half2(__float2half(e2), __float2half(e3));
        }
        __syncthreads();

        {
            float sum = 0.f;
#pragma unroll
            for (int t = quad * 16; t < quad * 16 + 16; t++)
                sum += Ss[lane64][t];
            part[quad][lane64] = sum;
        }
        __syncthreads();
        if (tid < 64)
            dsum[tid] = 1e-10f + ((part[0][tid] + part[1][tid])
                                + (part[2][tid] + part[3][tid]));
        __syncthreads();

        float oac[2][2][4];
#pragma unroll
        for (int mi = 0; mi < 2; mi++)
#pragma unroll
            for (int ni = 0; ni < 2; ni++)
#pragma unroll
                for (int e = 0; e < 4; e++) oac[mi][ni][e] = 0.f;
#pragma unroll
        for (int ks = 0; ks < 4; ks++) {
            uint32_t bf[4];
            ldsm_x4(bf, vb + (uint32_t)((wn * 16 + b_row) * HSB_ + ks * 32 + b_kb));
#pragma unroll
            for (int mi = 0; mi < 2; mi++) {
                uint32_t af[4];
                ldsm_x4(af, wb + (uint32_t)((wm * 32 + mi * 16 + a_row) * HSB_ + ks * 32 + a_kb));
                mma16816(oac[mi][0], af, &bf[0]);
                mma16816(oac[mi][1], af, &bf[2]);
            }
        }
#pragma unroll
        for (int mi = 0; mi < 2; mi++)
#pragma unroll
            for (int half = 0; half < 2; half++) {
                int q = ml + mi * 16 + half * 8;
                float inv = 1.0f / dsum[q];
                int m = s * SEG_ + n * 64 + q;
                size_t o = ((size_t)(b * M_ + m)) * DM_ + h * HD_;
#pragma unroll
                for (int ni = 0; ni < 2; ni++) {
                    int d = nl + ni * 8;
                    *(__half2*)&g_att_h[o + d] =
                        __halves2half2(__float2half(oac[mi][ni][half * 2] * inv),
                                       __float2half(oac[mi][ni][half * 2 + 1] * inv));
                }
            }
    }
}

// ---------------------------------------------------------------------------

extern "C" void kernel_launch(void* const* d_in, const int* in_sizes, int n_in,
                              void* d_out, int out_size) {
    const float* x    = (const float*)d_in[0];
    const float* Wqkv = (const float*)d_in[1];
    const float* Wout = (const float*)d_in[2];
    const int*   hmap = (const int*)d_in[3];
    float* out = (float*)d_out;
    (void)in_sizes; (void)n_in; (void)out_size;

    __half *xh, *qh, *oh, *ah;
    cudaGetSymbolAddress((void**)&xh, g_x_h);
    cudaGetSymbolAddress((void**)&qh, g_wqkv_h);
    cudaGetSymbolAddress((void**)&oh, g_wout_h);
    cudaGetSymbolAddress((void**)&ah, g_att_h);

    // 0) merged fp16 conversions
    prep_kernel<<<20480, 256>>>(x, Wqkv, Wout);

    cudaFuncSetAttribute((const void*)gemm_tc_kernel,
                         cudaFuncAttributeMaxDynamicSharedMemorySize, GEMM_SMEM);

    // 1) Merged Q + KV projection (2048 CTAs, 1-term, 2-stage)
    gemm_tc_kernel<<<2048, 256, GEMM_SMEM>>>(xh, qh, qh + 1024 * 1024,
                                             nullptr, 0, hmap);

    // 2) Hilbert segmented attention (tensor-core matmuls)
    cudaFuncSetAttribute((const void*)hilbert_attn_kernel,
                         cudaFuncAttributeMaxDynamicSharedMemorySize, ATT_SMEM);
    hilbert_attn_kernel<<<dim3(NSEG_, H_, B_), 256, ATT_SMEM>>>();

    // 3) Output projection (1024 CTAs, 1-term, 2-stage)
    gemm_tc_kernel<<<1024, 256, GEMM_SMEM>>>(ah, oh, nullptr, out, 1, hmap);
}